// round 7
// baseline (speedup 1.0000x reference)
#include <cuda_runtime.h>
#include <cuda_bf16.h>
#include <math.h>

// ---------------- problem constants ----------------
#define TT   128
#define BB   32
#define TB   (TT*BB)          // 4096
#define HID  128
#define FEAT 512
#define AA   18
#define OUTC (AA+1)           // 19

typedef unsigned long long u64;

// ---------------- packed f32x2 helpers (SASS FFMA2) ----------------
__device__ __forceinline__ u64 pk2(float x, float y) {
    u64 r; asm("mov.b64 %0, {%1, %2};" : "=l"(r) : "f"(x), "f"(y)); return r;
}
__device__ __forceinline__ u64 dup2(float x) { return pk2(x, x); }
__device__ __forceinline__ void ffma2(u64& d, u64 a, u64 b) {
    asm("fma.rn.f32x2 %0, %1, %2, %0;" : "+l"(d) : "l"(a), "l"(b));
}
__device__ __forceinline__ void upk2(u64 v, float& x, float& y) {
    asm("mov.b64 {%0, %1}, %2;" : "=f"(x), "=f"(y) : "l"(v));
}

// ---------------- scratch (static device allocations) ----------------
__device__ float g_c1[TB * 32 * 20 * 20];
__device__ float g_c2[TB * 64 * 9 * 9];
__device__ float g_c3[TB * 64 * 7 * 7];
__device__ float g_feat[TB * FEAT];
__device__ float g_gx[TB * 4 * HID];
__device__ float g_hid[TB * HID];
__device__ float g_w1r[8192];    // conv1 [r=256][oc=32], pre-scaled 1/255
__device__ float g_w2r[32768];   // conv2 [r=512][oc=64]
__device__ float g_w3r[36864];   // conv3 [r=576][oc=64]

// ============================================================
// weight reorder: out[r*OC + oc] = in[oc*R + r] * scale
// ============================================================
__global__ void reorder_w_kernel(const float* __restrict__ in,
                                 float* __restrict__ out,
                                 int R, int OC, float scale)
{
    int i = blockIdx.x * 256 + threadIdx.x;
    if (i >= R * OC) return;
    int oc = i / R, r = i - oc * R;
    out[r * OC + oc] = in[oc * R + r] * scale;
}

// ============================================================
// conv1: conv(4->32, 8x8, s4) -> relu.  84x84 -> 20x20
// 2 CTAs per image (10 output rows each). smem 91KB -> 2 CTAs/SM.
// 256 threads: ocg = t>>7 (2 groups of 16 oc), p = t&127 (<100 active),
// oyl = p/10, xg = p%10; 2 positions ox = xg*2+{0,1}.
// Per (ic,ky): 32 bcast weight LDS + 3 img LDS vs 128 FFMA2 -> fma-bound.
// Accumulation order per output unchanged -> bitwise-identical results.
// ============================================================
__global__ void __launch_bounds__(256, 2)
conv1_kernel(const float* __restrict__ x, const float* __restrict__ wr,
             const float* __restrict__ b, float* __restrict__ out)
{
    extern __shared__ float sm[];
    float* img = sm;            // 4 ch * 44 rows * 84 = 14784
    float* ws  = sm + 14784;    // [r=(ic*8+ky)*8+kx][oc=32]  8192

    const int n = blockIdx.x >> 1, half = blockIdx.x & 1;
    const int t = threadIdx.x;
    const int r0 = half * 40;

    const float4* xg4 = (const float4*)(x + (size_t)n * 28224);
    float4* img4 = (float4*)img;
#pragma unroll 4
    for (int i = t; i < 3696; i += 256) {
        int ch = i / 924, rr = i - ch * 924;
        img4[i] = xg4[ch * 1764 + r0 * 21 + rr];
    }
    const float4* wg = (const float4*)wr;
    float4* ws4 = (float4*)ws;
#pragma unroll
    for (int i = t; i < 2048; i += 256) ws4[i] = wg[i];
    __syncthreads();

    const int ocg = t >> 7, p = t & 127;
    if (p >= 100) return;
    const int oyl = p / 10, xg = p % 10;

    u64 acc[2][8];   // [pos][oc-pair], 16 oc per thread
#pragma unroll
    for (int q = 0; q < 8; ++q) {
        u64 bq = pk2(b[ocg * 16 + 2 * q], b[ocg * 16 + 2 * q + 1]);
        acc[0][q] = bq; acc[1][q] = bq;
    }

#pragma unroll
    for (int ic = 0; ic < 4; ++ic) {
#pragma unroll
        for (int ky = 0; ky < 8; ++ky) {
            const float* row = &img[ic * 3696 + (oyl * 4 + ky) * 84 + xg * 8];
            float rv[12];
            *(float4*)&rv[0] = *(const float4*)&row[0];
            *(float4*)&rv[4] = *(const float4*)&row[4];
            *(float4*)&rv[8] = *(const float4*)&row[8];
            const float* wb = &ws[((ic * 8 + ky) * 8) * 32 + ocg * 16];
#pragma unroll
            for (int kx = 0; kx < 8; ++kx) {
                ulonglong2 w01 = *(const ulonglong2*)&wb[kx * 32];
                ulonglong2 w23 = *(const ulonglong2*)&wb[kx * 32 + 4];
                ulonglong2 w45 = *(const ulonglong2*)&wb[kx * 32 + 8];
                ulonglong2 w67 = *(const ulonglong2*)&wb[kx * 32 + 12];
                u64 v0 = dup2(rv[kx]);
                u64 v1 = dup2(rv[4 + kx]);
                ffma2(acc[0][0], v0, w01.x); ffma2(acc[0][1], v0, w01.y);
                ffma2(acc[0][2], v0, w23.x); ffma2(acc[0][3], v0, w23.y);
                ffma2(acc[0][4], v0, w45.x); ffma2(acc[0][5], v0, w45.y);
                ffma2(acc[0][6], v0, w67.x); ffma2(acc[0][7], v0, w67.y);
                ffma2(acc[1][0], v1, w01.x); ffma2(acc[1][1], v1, w01.y);
                ffma2(acc[1][2], v1, w23.x); ffma2(acc[1][3], v1, w23.y);
                ffma2(acc[1][4], v1, w45.x); ffma2(acc[1][5], v1, w45.y);
                ffma2(acc[1][6], v1, w67.x); ffma2(acc[1][7], v1, w67.y);
            }
        }
    }
    float* op = out + (size_t)n * 12800 + (half * 10 + oyl) * 20 + xg * 2;
#pragma unroll
    for (int q = 0; q < 8; ++q) {
        float lo0, hi0, lo1, hi1;
        upk2(acc[0][q], lo0, hi0);
        upk2(acc[1][q], lo1, hi1);
        int oc0 = ocg * 16 + 2 * q;
        *(float2*)(op + (size_t)oc0 * 400)       = make_float2(fmaxf(lo0, 0.0f), fmaxf(lo1, 0.0f));
        *(float2*)(op + (size_t)(oc0 + 1) * 400) = make_float2(fmaxf(hi0, 0.0f), fmaxf(hi1, 0.0f));
    }
}

// ============================================================
// conv2: (32,20,20) -> (64,9,9), 4x4 s2, relu
// 512 threads (16 warps/SM vs 8 before): ocg = t>>6 (8 groups of 8 oc),
// sp = t&63 (<45 active): oy = sp/5, xg = sp%5; 2 positions ox = xg*2+{0,1}
// (xg=4 stores only ox=8). 4 images sequential per CTA.
// smem padded +4 floats: xg=4 loads 8 floats from row base col 16 (of 20).
// ============================================================
__global__ void __launch_bounds__(512, 1)
conv2_kernel(const float* __restrict__ in, const float* __restrict__ wr,
             const float* __restrict__ b, float* __restrict__ out)
{
    extern __shared__ float sm[];
    float* ws  = sm;            // [r=(ic*4+ky)*4+kx][oc=64]  32768 floats
    float* img = sm + 32768;    // 12800 floats (+4 pad at end)

    const int t = threadIdx.x;
    const float4* wg = (const float4*)wr;
    float4* ws4 = (float4*)ws;
#pragma unroll
    for (int i = t; i < 8192; i += 512) ws4[i] = wg[i];

    const int ocg = t >> 6, sp = t & 63;
    const bool act = sp < 45;
    const int oy = sp / 5, xg = sp % 5;
    const bool two = xg < 4;

    u64 bia[4];
#pragma unroll
    for (int q = 0; q < 4; ++q)
        bia[q] = pk2(b[ocg * 8 + 2 * q], b[ocg * 8 + 2 * q + 1]);

    for (int im = 0; im < 4; ++im) {
        const int n = blockIdx.x * 4 + im;
        __syncthreads();
        const float4* ig = (const float4*)(in + (size_t)n * 12800);
        float4* img4 = (float4*)img;
#pragma unroll
        for (int i = t; i < 3200; i += 512) img4[i] = ig[i];
        __syncthreads();

        if (act) {
            u64 acc[2][4];   // [pos][oc-pair]
#pragma unroll
            for (int q = 0; q < 4; ++q) { acc[0][q] = bia[q]; acc[1][q] = bia[q]; }

            for (int ic = 0; ic < 32; ++ic) {
#pragma unroll
                for (int ky = 0; ky < 4; ++ky) {
                    // input cols needed: xg*4 + (0..5); load 8 (aligned)
                    const float* row = &img[ic * 400 + (oy * 2 + ky) * 20 + xg * 4];
                    float rv[8];
                    *(float4*)&rv[0] = *(const float4*)&row[0];
                    *(float4*)&rv[4] = *(const float4*)&row[4];
                    const float* wb = &ws[((ic * 4 + ky) * 4) * 64 + ocg * 8];
#pragma unroll
                    for (int kx = 0; kx < 4; ++kx) {
                        ulonglong2 w01 = *(const ulonglong2*)&wb[kx * 64];
                        ulonglong2 w23 = *(const ulonglong2*)&wb[kx * 64 + 4];
                        u64 v0 = dup2(rv[kx]);
                        u64 v1 = dup2(rv[2 + kx]);
                        ffma2(acc[0][0], v0, w01.x); ffma2(acc[0][1], v0, w01.y);
                        ffma2(acc[0][2], v0, w23.x); ffma2(acc[0][3], v0, w23.y);
                        ffma2(acc[1][0], v1, w01.x); ffma2(acc[1][1], v1, w01.y);
                        ffma2(acc[1][2], v1, w23.x); ffma2(acc[1][3], v1, w23.y);
                    }
                }
            }
            float* op = out + (size_t)n * 5184 + oy * 9 + xg * 2;
#pragma unroll
            for (int q = 0; q < 4; ++q) {
                float lo0, hi0, lo1, hi1;
                upk2(acc[0][q], lo0, hi0);
                upk2(acc[1][q], lo1, hi1);
                int oc0 = ocg * 8 + 2 * q;
                op[(size_t)oc0 * 81]       = fmaxf(lo0, 0.0f);
                op[(size_t)(oc0 + 1) * 81] = fmaxf(hi0, 0.0f);
                if (two) {
                    op[(size_t)oc0 * 81 + 1]       = fmaxf(lo1, 0.0f);
                    op[(size_t)(oc0 + 1) * 81 + 1] = fmaxf(hi1, 0.0f);
                }
            }
        }
    }
}

// ============================================================
// conv3: (64,9,9) -> (64,7,7), 3x3 s1, relu
// 512 threads: ocg = t>>5 (16 groups of 4 oc), sub = t&31,
// imgi = sub>>3 (4 concurrent images), oy = sub&7 (<7 active).
// Image buffers padded to 5188 floats.
// ============================================================
#define C3_IMG_STRIDE 5188

__global__ void __launch_bounds__(512, 1)
conv3_kernel(const float* __restrict__ in, const float* __restrict__ wr,
             const float* __restrict__ b, float* __restrict__ out)
{
    extern __shared__ float sm[];
    float* ws  = sm;                 // 36864 floats
    float* img = sm + 36864;         // 4 * 5188 floats

    const int t = threadIdx.x;
    const float4* wg = (const float4*)wr;
    float4* ws4 = (float4*)ws;
#pragma unroll
    for (int i = t; i < 9216; i += 512) ws4[i] = wg[i];

    const int n0 = blockIdx.x * 4;
    const float4* ig = (const float4*)(in + (size_t)n0 * 5184);
#pragma unroll
    for (int i = t; i < 5184; i += 512) {
        int im = i / 1296, rr = i - im * 1296;
        ((float4*)(img + im * C3_IMG_STRIDE))[rr] = ig[im * 1296 + rr];
    }
    __syncthreads();

    const int ocg = t >> 5, sub = t & 31;
    const int imgi = sub >> 3, oy = sub & 7;
    if (oy >= 7) return;

    u64 bia[2];
    bia[0] = pk2(b[ocg * 4 + 0], b[ocg * 4 + 1]);
    bia[1] = pk2(b[ocg * 4 + 2], b[ocg * 4 + 3]);

    const float* ib = &img[imgi * C3_IMG_STRIDE];
    u64 acc[7][2];
#pragma unroll
    for (int i = 0; i < 7; ++i) { acc[i][0] = bia[0]; acc[i][1] = bia[1]; }

    for (int ic = 0; ic < 64; ++ic) {
#pragma unroll
        for (int ky = 0; ky < 3; ++ky) {
            const float* row = &ib[ic * 81 + (oy + ky) * 9];
            u64 rd[9];
#pragma unroll
            for (int c = 0; c < 9; ++c) rd[c] = dup2(row[c]);
            const float* wb = &ws[(ic * 9 + ky * 3) * 64 + ocg * 4];
#pragma unroll
            for (int kx = 0; kx < 3; ++kx) {
                ulonglong2 wv = *(const ulonglong2*)&wb[kx * 64];
#pragma unroll
                for (int ox = 0; ox < 7; ++ox) {
                    ffma2(acc[ox][0], rd[ox + kx], wv.x);
                    ffma2(acc[ox][1], rd[ox + kx], wv.y);
                }
            }
        }
    }
    float* op = out + (size_t)(n0 + imgi) * 3136 + oy * 7;
#pragma unroll
    for (int q = 0; q < 2; ++q) {
#pragma unroll
        for (int ox = 0; ox < 7; ++ox) {
            float lo, hi; upk2(acc[ox][q], lo, hi);
            op[(ocg * 4 + 2 * q + 0) * 49 + ox] = fmaxf(lo, 0.0f);
            op[(ocg * 4 + 2 * q + 1) * 49 + ox] = fmaxf(hi, 0.0f);
        }
    }
}

// ============================================================
// GEMM: C[M,N] = A[M,K] @ B[N,K]^T + bias1 (+bias2), optional ReLU
// 128x64 tiles, 128 threads, 8(M)x8(N) micro-tiles, f32x2 FMA.
// occupancy 4 (6 would cap regs at 85 and spill accumulators).
// ============================================================
template <bool RELU, bool BIAS2>
__global__ void __launch_bounds__(128, 4)
gemm_kernel(const float* __restrict__ A, const float* __restrict__ B,
            const float* __restrict__ bias1, const float* __restrict__ bias2,
            float* __restrict__ C, int M, int N, int K)
{
    __shared__ float As[16][128];
    __shared__ float Bs[16][64];

    const int tid = threadIdx.x;
    const int tx = tid & 7, ty = tid >> 3;
    const int bm = blockIdx.y * 128;
    const int bn = blockIdx.x * 64;

    u64 acc[4][8];
#pragma unroll
    for (int i = 0; i < 4; ++i)
#pragma unroll
        for (int q = 0; q < 8; ++q) acc[i][q] = 0ull;

    for (int kb = 0; kb < K; kb += 16) {
#pragma unroll
        for (int h = 0; h < 4; ++h) {
            int f = tid + h * 128;
            int row = f >> 2, kc4 = (f & 3) * 4;
            float4 av = *(const float4*)(A + (size_t)(bm + row) * K + kb + kc4);
            As[kc4 + 0][row] = av.x; As[kc4 + 1][row] = av.y;
            As[kc4 + 2][row] = av.z; As[kc4 + 3][row] = av.w;
        }
#pragma unroll
        for (int h = 0; h < 2; ++h) {
            int f = tid + h * 128;
            int row = f >> 2, kc4 = (f & 3) * 4;
            float4 bv = *(const float4*)(B + (size_t)(bn + row) * K + kb + kc4);
            Bs[kc4 + 0][row] = bv.x; Bs[kc4 + 1][row] = bv.y;
            Bs[kc4 + 2][row] = bv.z; Bs[kc4 + 3][row] = bv.w;
        }
        __syncthreads();

#pragma unroll
        for (int kk = 0; kk < 16; ++kk) {
            ulonglong2 a01 = *(const ulonglong2*)&As[kk][ty * 8];
            ulonglong2 a23 = *(const ulonglong2*)&As[kk][ty * 8 + 4];
            float4 b0 = *(const float4*)&Bs[kk][tx * 8];
            float4 b1 = *(const float4*)&Bs[kk][tx * 8 + 4];
            u64 bd[8];
            bd[0] = dup2(b0.x); bd[1] = dup2(b0.y);
            bd[2] = dup2(b0.z); bd[3] = dup2(b0.w);
            bd[4] = dup2(b1.x); bd[5] = dup2(b1.y);
            bd[6] = dup2(b1.z); bd[7] = dup2(b1.w);
            u64 ap[4] = {a01.x, a01.y, a23.x, a23.y};
#pragma unroll
            for (int i = 0; i < 4; ++i)
#pragma unroll
                for (int q = 0; q < 8; ++q) ffma2(acc[i][q], ap[i], bd[q]);
        }
        __syncthreads();
    }

    float bv[8];
#pragma unroll
    for (int q = 0; q < 8; ++q) {
        bv[q] = bias1[bn + tx * 8 + q];
        if (BIAS2) bv[q] += bias2[bn + tx * 8 + q];
    }
#pragma unroll
    for (int i = 0; i < 4; ++i) {
        float lo[8], hi[8];
#pragma unroll
        for (int q = 0; q < 8; ++q) {
            upk2(acc[i][q], lo[q], hi[q]);
            lo[q] += bv[q]; hi[q] += bv[q];
            if (RELU) { lo[q] = fmaxf(lo[q], 0.0f); hi[q] = fmaxf(hi[q], 0.0f); }
        }
        float* c0 = C + (size_t)(bm + ty * 8 + 2 * i) * N + bn + tx * 8;
        float* c1 = c0 + N;
        *(float4*)(c0 + 0) = make_float4(lo[0], lo[1], lo[2], lo[3]);
        *(float4*)(c0 + 4) = make_float4(lo[4], lo[5], lo[6], lo[7]);
        *(float4*)(c1 + 0) = make_float4(hi[0], hi[1], hi[2], hi[3]);
        *(float4*)(c1 + 4) = make_float4(hi[4], hi[5], hi[6], hi[7]);
    }
}

// ============================================================
// LSTM recurrence: one CTA per env (32 CTAs), 512 threads.
// ============================================================
#define LSTM_SMEM_BYTES (16 * 512 * 16 + 128 * 4 + 512 * 4)

__global__ void __launch_bounds__(512, 1)
lstm_kernel(const float* __restrict__ gx, const float* __restrict__ whh,
            const int* __restrict__ done, const float* __restrict__ h0,
            const float* __restrict__ c0, float* __restrict__ hid)
{
    extern __shared__ float sm[];
    float4* wp4  = (float4*)sm;                    // [16][512] float4
    float*  h_sh = sm + 16 * 512 * 4;              // 128
    float*  act  = h_sh + 128;                     // 512

    const int env = blockIdx.x;
    const int j = threadIdx.x;

    const float* wrow = whh + (size_t)j * 128;
    float wreg[64];
#pragma unroll
    for (int k = 0; k < 64; k += 4) {
        float4 v = *(const float4*)(wrow + k);
        wreg[k] = v.x; wreg[k + 1] = v.y; wreg[k + 2] = v.z; wreg[k + 3] = v.w;
    }
#pragma unroll
    for (int kk = 0; kk < 16; ++kk)
        wp4[kk * 512 + j] = *(const float4*)(wrow + 64 + kk * 4);

    float c = 0.0f, hprev = 0.0f;
    if (j < 128) {
        hprev = h0[env * 128 + j];
        c     = c0[env * 128 + j];
    }
    __syncthreads();

    for (int t = 0; t < TT; ++t) {
        if (j < 128) {
            float m = 1.0f - (float)done[t * BB + env];
            h_sh[j] = hprev * m;
            c *= m;
        }
        __syncthreads();

        float accv = gx[((size_t)t * BB + env) * 512 + j];
#pragma unroll
        for (int k = 0; k < 64; k += 4) {
            float4 hv = *(const float4*)&h_sh[k];
            accv += hv.x * wreg[k] + hv.y * wreg[k + 1]
                  + hv.z * wreg[k + 2] + hv.w * wreg[k + 3];
        }
#pragma unroll
        for (int kk = 0; kk < 16; ++kk) {
            float4 wv = wp4[kk * 512 + j];
            float4 hv = *(const float4*)&h_sh[64 + kk * 4];
            accv += wv.x * hv.x + wv.y * hv.y + wv.z * hv.z + wv.w * hv.w;
        }

        float a;
        if (j < 256 || j >= 384) a = 1.0f / (1.0f + expf(-accv));
        else                     a = tanhf(accv);
        act[j] = a;
        __syncthreads();

        if (j < 128) {
            float ig = act[j],       fg = act[128 + j];
            float gg = act[256 + j], og = act[384 + j];
            c = fg * c + ig * gg;
            hprev = og * tanhf(c);
            hid[((size_t)t * BB + env) * 128 + j] = hprev;
        }
    }
}

// ============================================================
// heads
// ============================================================
__global__ void __launch_bounds__(304, 4)
heads_kernel(const float* __restrict__ hid, const float* __restrict__ wa,
             const float* __restrict__ ba, const float* __restrict__ wc,
             const float* __restrict__ bc, float* __restrict__ out)
{
    __shared__ float wsh[19 * 128];
    __shared__ float hsh[16 * 128];
    __shared__ float bsh[19];

    const int t = threadIdx.x;
    const int rb = blockIdx.x * 16;

    for (int i = t; i < 18 * 128; i += 304) wsh[i] = wa[i];
    for (int i = t; i < 128; i += 304)      wsh[18 * 128 + i] = wc[i];
    for (int i = t; i < 2048; i += 304)     hsh[i] = hid[(size_t)rb * 128 + i];
    if (t < 18) bsh[t] = ba[t];
    if (t == 18) bsh[18] = bc[0];
    __syncthreads();

    const int r = t / 19, cidx = t % 19;
    float accv = bsh[cidx];
    const float* hr = &hsh[r * 128];
    const float* wr = &wsh[cidx * 128];
#pragma unroll
    for (int k = 0; k < 128; k += 4) {
        float4 hv = *(const float4*)(hr + k);
        float4 wv = *(const float4*)(wr + k);
        accv += hv.x * wv.x + hv.y * wv.y + hv.z * wv.z + hv.w * wv.w;
    }
    out[(size_t)(rb + r) * OUTC + cidx] = accv;
}

// ============================================================
// host launcher
// ============================================================
extern "C" void kernel_launch(void* const* d_in, const int* in_sizes, int n_in,
                              void* d_out, int out_size)
{
    const float* x    = (const float*)d_in[0];
    const int*   done = (const int*)  d_in[1];
    const float* h0   = (const float*)d_in[2];
    const float* c0   = (const float*)d_in[3];
    const float* w1   = (const float*)d_in[4];
    const float* b1   = (const float*)d_in[5];
    const float* w2   = (const float*)d_in[6];
    const float* b2   = (const float*)d_in[7];
    const float* w3   = (const float*)d_in[8];
    const float* b3   = (const float*)d_in[9];
    const float* wf   = (const float*)d_in[10];
    const float* bf   = (const float*)d_in[11];
    const float* w_ih = (const float*)d_in[12];
    const float* w_hh = (const float*)d_in[13];
    const float* b_ih = (const float*)d_in[14];
    const float* b_hh = (const float*)d_in[15];
    const float* wa   = (const float*)d_in[16];
    const float* ba   = (const float*)d_in[17];
    const float* wc   = (const float*)d_in[18];
    const float* bc   = (const float*)d_in[19];
    float* out = (float*)d_out;

    float *c1, *c2, *c3, *feat, *gx, *hidp, *w1r, *w2r, *w3r;
    cudaGetSymbolAddress((void**)&c1,   g_c1);
    cudaGetSymbolAddress((void**)&c2,   g_c2);
    cudaGetSymbolAddress((void**)&c3,   g_c3);
    cudaGetSymbolAddress((void**)&feat, g_feat);
    cudaGetSymbolAddress((void**)&gx,   g_gx);
    cudaGetSymbolAddress((void**)&hidp, g_hid);
    cudaGetSymbolAddress((void**)&w1r,  g_w1r);
    cudaGetSymbolAddress((void**)&w2r,  g_w2r);
    cudaGetSymbolAddress((void**)&w3r,  g_w3r);

    const int c1_smem = (14784 + 8192) * 4;               // 91904
    const int c2_smem = (32768 + 12800 + 4) * 4;          // 182288 (+pad)
    const int c3_smem = (36864 + 4 * C3_IMG_STRIDE) * 4;  // 230464
    cudaFuncSetAttribute(conv1_kernel, cudaFuncAttributeMaxDynamicSharedMemorySize, c1_smem);
    cudaFuncSetAttribute(conv2_kernel, cudaFuncAttributeMaxDynamicSharedMemorySize, c2_smem);
    cudaFuncSetAttribute(conv3_kernel, cudaFuncAttributeMaxDynamicSharedMemorySize, c3_smem);
    cudaFuncSetAttribute(lstm_kernel,  cudaFuncAttributeMaxDynamicSharedMemorySize, LSTM_SMEM_BYTES);

    reorder_w_kernel<<<(8192  + 255) / 256, 256>>>(w1, w1r, 256, 32, 1.0f / 255.0f);
    reorder_w_kernel<<<(32768 + 255) / 256, 256>>>(w2, w2r, 512, 64, 1.0f);
    reorder_w_kernel<<<(36864 + 255) / 256, 256>>>(w3, w3r, 576, 64, 1.0f);

    conv1_kernel<<<TB * 2, 256, c1_smem>>>(x, w1r, b1, c1);
    conv2_kernel<<<TB / 4, 512, c2_smem>>>(c1, w2r, b2, c2);
    conv3_kernel<<<TB / 4, 512, c3_smem>>>(c2, w3r, b3, c3);

    gemm_kernel<true, false><<<dim3(FEAT / 64, TB / 128), 128>>>(
        c3, wf, bf, nullptr, feat, TB, FEAT, 3136);

    gemm_kernel<false, true><<<dim3(512 / 64, TB / 128), 128>>>(
        feat, w_ih, b_ih, b_hh, gx, TB, 512, FEAT);

    lstm_kernel<<<BB, 512, LSTM_SMEM_BYTES>>>(gx, w_hh, done, h0, c0, hidp);

    heads_kernel<<<TB / 16, 304>>>(hidp, wa, ba, wc, bc, out);
}

// round 8
// speedup vs baseline: 1.1204x; 1.1204x over previous
#include <cuda_runtime.h>
#include <cuda_bf16.h>
#include <math.h>

// ---------------- problem constants ----------------
#define TT   128
#define BB   32
#define TB   (TT*BB)          // 4096
#define HID  128
#define FEAT 512
#define AA   18
#define OUTC (AA+1)           // 19

typedef unsigned long long u64;

// ---------------- packed f32x2 helpers (SASS FFMA2) ----------------
__device__ __forceinline__ u64 pk2(float x, float y) {
    u64 r; asm("mov.b64 %0, {%1, %2};" : "=l"(r) : "f"(x), "f"(y)); return r;
}
__device__ __forceinline__ u64 dup2(float x) { return pk2(x, x); }
__device__ __forceinline__ void ffma2(u64& d, u64 a, u64 b) {
    asm("fma.rn.f32x2 %0, %1, %2, %0;" : "+l"(d) : "l"(a), "l"(b));
}
__device__ __forceinline__ void upk2(u64 v, float& x, float& y) {
    asm("mov.b64 {%0, %1}, %2;" : "=f"(x), "=f"(y) : "l"(v));
}

// ---------------- scratch (static device allocations) ----------------
__device__ float g_c1[TB * 32 * 20 * 20];
__device__ float g_c2[TB * 64 * 9 * 9];
__device__ float g_c3[TB * 64 * 7 * 7];
__device__ float g_feat[TB * FEAT];
__device__ float g_gx[TB * 4 * HID];
__device__ float g_hid[TB * HID];
__device__ float g_w1r[8192];    // conv1 [r=256][oc=32], pre-scaled 1/255
__device__ float g_w2r[32768];   // conv2 [r=512][oc=64]
__device__ float g_w3r[36864];   // conv3 [r=576][oc=64]

// ============================================================
// weight reorder: out[r*OC + oc] = in[oc*R + r] * scale
// ============================================================
__global__ void reorder_w_kernel(const float* __restrict__ in,
                                 float* __restrict__ out,
                                 int R, int OC, float scale)
{
    int i = blockIdx.x * 256 + threadIdx.x;
    if (i >= R * OC) return;
    int oc = i / R, r = i - oc * R;
    out[r * OC + oc] = in[oc * R + r] * scale;
}

// ============================================================
// conv1 [R6 version, measured 693us]: conv(4->32, 8x8, s4) -> relu.
// 2 CTAs per image (10 output rows each). smem 91KB -> 2 CTAs/SM.
// 512 threads: ocg = t>>7 (4 groups of 8 oc), p = t&127 (<100 active),
// oyl = p/10, xg = p%10; 2 positions ox = xg*2+{0,1}.
// ============================================================
__global__ void __launch_bounds__(512, 2)
conv1_kernel(const float* __restrict__ x, const float* __restrict__ wr,
             const float* __restrict__ b, float* __restrict__ out)
{
    extern __shared__ float sm[];
    float* img = sm;            // 4 ch * 44 rows * 84 = 14784
    float* ws  = sm + 14784;    // [r=(ic*8+ky)*8+kx][oc=32]  8192

    const int n = blockIdx.x >> 1, half = blockIdx.x & 1;
    const int t = threadIdx.x;
    const int r0 = half * 40;

    const float4* xg4 = (const float4*)(x + (size_t)n * 28224);
    float4* img4 = (float4*)img;
#pragma unroll 4
    for (int i = t; i < 3696; i += 512) {
        int ch = i / 924, rr = i - ch * 924;
        img4[i] = xg4[ch * 1764 + r0 * 21 + rr];
    }
    const float4* wg = (const float4*)wr;
    float4* ws4 = (float4*)ws;
#pragma unroll
    for (int i = t; i < 2048; i += 512) ws4[i] = wg[i];
    __syncthreads();

    const int ocg = t >> 7, p = t & 127;
    if (p >= 100) return;
    const int oyl = p / 10, xg = p % 10;

    u64 acc[2][4];
#pragma unroll
    for (int q = 0; q < 4; ++q) {
        u64 bq = pk2(b[ocg * 8 + 2 * q], b[ocg * 8 + 2 * q + 1]);
        acc[0][q] = bq; acc[1][q] = bq;
    }

#pragma unroll
    for (int ic = 0; ic < 4; ++ic) {
#pragma unroll
        for (int ky = 0; ky < 8; ++ky) {
            const float* row = &img[ic * 3696 + (oyl * 4 + ky) * 84 + xg * 8];
            float rv[12];
            *(float4*)&rv[0] = *(const float4*)&row[0];
            *(float4*)&rv[4] = *(const float4*)&row[4];
            *(float4*)&rv[8] = *(const float4*)&row[8];
            const float* wb = &ws[((ic * 8 + ky) * 8) * 32 + ocg * 8];
#pragma unroll
            for (int kx = 0; kx < 8; ++kx) {
                ulonglong2 w01 = *(const ulonglong2*)&wb[kx * 32];
                ulonglong2 w23 = *(const ulonglong2*)&wb[kx * 32 + 4];
                u64 v0 = dup2(rv[kx]);
                u64 v1 = dup2(rv[4 + kx]);
                ffma2(acc[0][0], v0, w01.x); ffma2(acc[0][1], v0, w01.y);
                ffma2(acc[0][2], v0, w23.x); ffma2(acc[0][3], v0, w23.y);
                ffma2(acc[1][0], v1, w01.x); ffma2(acc[1][1], v1, w01.y);
                ffma2(acc[1][2], v1, w23.x); ffma2(acc[1][3], v1, w23.y);
            }
        }
    }
    float* op = out + (size_t)n * 12800 + (half * 10 + oyl) * 20 + xg * 2;
#pragma unroll
    for (int q = 0; q < 4; ++q) {
        float lo0, hi0, lo1, hi1;
        upk2(acc[0][q], lo0, hi0);
        upk2(acc[1][q], lo1, hi1);
        int oc0 = ocg * 8 + 2 * q;
        *(float2*)(op + (size_t)oc0 * 400)       = make_float2(fmaxf(lo0, 0.0f), fmaxf(lo1, 0.0f));
        *(float2*)(op + (size_t)(oc0 + 1) * 400) = make_float2(fmaxf(hi0, 0.0f), fmaxf(hi1, 0.0f));
    }
}

// ============================================================
// conv2 [R6/R3 version, known-good]: (32,20,20) -> (64,9,9), 4x4 s2, relu
// 256 threads: ocg = t>>5 (8 groups of 8 oc), sp = t&31 (<27 active),
// oy = sp/3, xg = sp%3; 3 positions each. 4 images sequential per CTA.
// ============================================================
__global__ void __launch_bounds__(256, 1)
conv2_kernel(const float* __restrict__ in, const float* __restrict__ wr,
             const float* __restrict__ b, float* __restrict__ out)
{
    extern __shared__ float sm[];
    float* ws  = sm;            // 32768 floats
    float* img = sm + 32768;    // 12800 floats

    const int t = threadIdx.x;
    const float4* wg = (const float4*)wr;
    float4* ws4 = (float4*)ws;
#pragma unroll
    for (int i = t; i < 8192; i += 256) ws4[i] = wg[i];

    const int ocg = t >> 5, sp = t & 31;
    const bool act = sp < 27;
    const int oy = sp / 3, xg = sp % 3;

    u64 bia[4];
#pragma unroll
    for (int q = 0; q < 4; ++q)
        bia[q] = pk2(b[ocg * 8 + 2 * q], b[ocg * 8 + 2 * q + 1]);

    for (int im = 0; im < 4; ++im) {
        const int n = blockIdx.x * 4 + im;
        __syncthreads();
        const float4* ig = (const float4*)(in + (size_t)n * 12800);
        float4* img4 = (float4*)img;
#pragma unroll
        for (int i = t; i < 3200; i += 256) img4[i] = ig[i];
        __syncthreads();

        if (act) {
            u64 acc[3][4];
#pragma unroll
            for (int i = 0; i < 3; ++i)
#pragma unroll
                for (int q = 0; q < 4; ++q) acc[i][q] = bia[q];

            for (int ic = 0; ic < 32; ++ic) {
#pragma unroll
                for (int ky = 0; ky < 4; ++ky) {
                    const float* row = &img[ic * 400 + (oy * 2 + ky) * 20 + xg * 6];
                    float rv[8];
#pragma unroll
                    for (int j = 0; j < 4; ++j)
                        *(float2*)&rv[j * 2] = *(const float2*)&row[j * 2];
                    const float* wb = &ws[((ic * 4 + ky) * 4) * 64 + ocg * 8];
#pragma unroll
                    for (int kx = 0; kx < 4; ++kx) {
                        ulonglong2 w01 = *(const ulonglong2*)&wb[kx * 64];
                        ulonglong2 w23 = *(const ulonglong2*)&wb[kx * 64 + 4];
#pragma unroll
                        for (int i = 0; i < 3; ++i) {
                            u64 v = dup2(rv[i * 2 + kx]);
                            ffma2(acc[i][0], v, w01.x);
                            ffma2(acc[i][1], v, w01.y);
                            ffma2(acc[i][2], v, w23.x);
                            ffma2(acc[i][3], v, w23.y);
                        }
                    }
                }
            }
            float* op = out + (size_t)n * 5184 + oy * 9 + xg * 3;
#pragma unroll
            for (int q = 0; q < 4; ++q) {
#pragma unroll
                for (int i = 0; i < 3; ++i) {
                    float lo, hi; upk2(acc[i][q], lo, hi);
                    op[(ocg * 8 + 2 * q + 0) * 81 + i] = fmaxf(lo, 0.0f);
                    op[(ocg * 8 + 2 * q + 1) * 81 + i] = fmaxf(hi, 0.0f);
                }
            }
        }
    }
}

// ============================================================
// conv3 [R6 version]: (64,9,9) -> (64,7,7), 3x3 s1, relu
// 512 threads: 16 oc-groups of 4 oc, 4 concurrent images (stride 5188).
// ============================================================
#define C3_IMG_STRIDE 5188

__global__ void __launch_bounds__(512, 1)
conv3_kernel(const float* __restrict__ in, const float* __restrict__ wr,
             const float* __restrict__ b, float* __restrict__ out)
{
    extern __shared__ float sm[];
    float* ws  = sm;                 // 36864 floats
    float* img = sm + 36864;         // 4 * 5188 floats

    const int t = threadIdx.x;
    const float4* wg = (const float4*)wr;
    float4* ws4 = (float4*)ws;
#pragma unroll
    for (int i = t; i < 9216; i += 512) ws4[i] = wg[i];

    const int n0 = blockIdx.x * 4;
    const float4* ig = (const float4*)(in + (size_t)n0 * 5184);
#pragma unroll
    for (int i = t; i < 5184; i += 512) {
        int im = i / 1296, rr = i - im * 1296;
        ((float4*)(img + im * C3_IMG_STRIDE))[rr] = ig[im * 1296 + rr];
    }
    __syncthreads();

    const int ocg = t >> 5, sub = t & 31;
    const int imgi = sub >> 3, oy = sub & 7;
    if (oy >= 7) return;

    u64 bia[2];
    bia[0] = pk2(b[ocg * 4 + 0], b[ocg * 4 + 1]);
    bia[1] = pk2(b[ocg * 4 + 2], b[ocg * 4 + 3]);

    const float* ib = &img[imgi * C3_IMG_STRIDE];
    u64 acc[7][2];
#pragma unroll
    for (int i = 0; i < 7; ++i) { acc[i][0] = bia[0]; acc[i][1] = bia[1]; }

    for (int ic = 0; ic < 64; ++ic) {
#pragma unroll
        for (int ky = 0; ky < 3; ++ky) {
            const float* row = &ib[ic * 81 + (oy + ky) * 9];
            u64 rd[9];
#pragma unroll
            for (int c = 0; c < 9; ++c) rd[c] = dup2(row[c]);
            const float* wb = &ws[(ic * 9 + ky * 3) * 64 + ocg * 4];
#pragma unroll
            for (int kx = 0; kx < 3; ++kx) {
                ulonglong2 wv = *(const ulonglong2*)&wb[kx * 64];
#pragma unroll
                for (int ox = 0; ox < 7; ++ox) {
                    ffma2(acc[ox][0], rd[ox + kx], wv.x);
                    ffma2(acc[ox][1], rd[ox + kx], wv.y);
                }
            }
        }
    }
    float* op = out + (size_t)(n0 + imgi) * 3136 + oy * 7;
#pragma unroll
    for (int q = 0; q < 2; ++q) {
#pragma unroll
        for (int ox = 0; ox < 7; ++ox) {
            float lo, hi; upk2(acc[ox][q], lo, hi);
            op[(ocg * 4 + 2 * q + 0) * 49 + ox] = fmaxf(lo, 0.0f);
            op[(ocg * 4 + 2 * q + 1) * 49 + ox] = fmaxf(hi, 0.0f);
        }
    }
}

// ============================================================
// GEMM: C[M,N] = A[M,K] @ B[N,K]^T + bias1 (+bias2), optional ReLU
// 128x64 tiles, 128 threads, 8(M)x8(N) micro-tiles, f32x2 FMA.
// DOUBLE-BUFFERED: LDG(next) overlaps compute(cur); 1 sync/iter.
// Accumulation order identical to single-buffer version.
// ============================================================
template <bool RELU, bool BIAS2>
__global__ void __launch_bounds__(128, 4)
gemm_kernel(const float* __restrict__ A, const float* __restrict__ B,
            const float* __restrict__ bias1, const float* __restrict__ bias2,
            float* __restrict__ C, int M, int N, int K)
{
    __shared__ float As[2][16][128];
    __shared__ float Bs[2][16][64];

    const int tid = threadIdx.x;
    const int tx = tid & 7, ty = tid >> 3;
    const int bm = blockIdx.y * 128;
    const int bn = blockIdx.x * 64;

    // per-thread staging coordinates
    const int arow0 = tid >> 2, akc = (tid & 3) * 4;   // +h*32 rows, h=0..3
    const int brow0 = tid >> 2, bkc = (tid & 3) * 4;   // +h*32 rows, h=0..1

    u64 acc[4][8];
#pragma unroll
    for (int i = 0; i < 4; ++i)
#pragma unroll
        for (int q = 0; q < 8; ++q) acc[i][q] = 0ull;

    float4 ar[4], br[2];

    // prologue: tile 0 -> regs -> smem[0]
#pragma unroll
    for (int h = 0; h < 4; ++h)
        ar[h] = *(const float4*)(A + (size_t)(bm + arow0 + h * 32) * K + akc);
#pragma unroll
    for (int h = 0; h < 2; ++h)
        br[h] = *(const float4*)(B + (size_t)(bn + brow0 + h * 32) * K + bkc);
#pragma unroll
    for (int h = 0; h < 4; ++h) {
        int row = arow0 + h * 32;
        As[0][akc + 0][row] = ar[h].x; As[0][akc + 1][row] = ar[h].y;
        As[0][akc + 2][row] = ar[h].z; As[0][akc + 3][row] = ar[h].w;
    }
#pragma unroll
    for (int h = 0; h < 2; ++h) {
        int row = brow0 + h * 32;
        Bs[0][bkc + 0][row] = br[h].x; Bs[0][bkc + 1][row] = br[h].y;
        Bs[0][bkc + 2][row] = br[h].z; Bs[0][bkc + 3][row] = br[h].w;
    }
    __syncthreads();

    int cur = 0;
    for (int kb = 16; kb < K; kb += 16) {
        // LDG next tile into regs (overlaps with compute below)
#pragma unroll
        for (int h = 0; h < 4; ++h)
            ar[h] = *(const float4*)(A + (size_t)(bm + arow0 + h * 32) * K + kb + akc);
#pragma unroll
        for (int h = 0; h < 2; ++h)
            br[h] = *(const float4*)(B + (size_t)(bn + brow0 + h * 32) * K + kb + bkc);

        // compute current buffer
#pragma unroll
        for (int kk = 0; kk < 16; ++kk) {
            ulonglong2 a01 = *(const ulonglong2*)&As[cur][kk][ty * 8];
            ulonglong2 a23 = *(const ulonglong2*)&As[cur][kk][ty * 8 + 4];
            float4 b0 = *(const float4*)&Bs[cur][kk][tx * 8];
            float4 b1 = *(const float4*)&Bs[cur][kk][tx * 8 + 4];
            u64 bd[8];
            bd[0] = dup2(b0.x); bd[1] = dup2(b0.y);
            bd[2] = dup2(b0.z); bd[3] = dup2(b0.w);
            bd[4] = dup2(b1.x); bd[5] = dup2(b1.y);
            bd[6] = dup2(b1.z); bd[7] = dup2(b1.w);
            u64 ap[4] = {a01.x, a01.y, a23.x, a23.y};
#pragma unroll
            for (int i = 0; i < 4; ++i)
#pragma unroll
                for (int q = 0; q < 8; ++q) ffma2(acc[i][q], ap[i], bd[q]);
        }

        // stage next into the other buffer (nobody is reading it)
        int nxt = cur ^ 1;
#pragma unroll
        for (int h = 0; h < 4; ++h) {
            int row = arow0 + h * 32;
            As[nxt][akc + 0][row] = ar[h].x; As[nxt][akc + 1][row] = ar[h].y;
            As[nxt][akc + 2][row] = ar[h].z; As[nxt][akc + 3][row] = ar[h].w;
        }
#pragma unroll
        for (int h = 0; h < 2; ++h) {
            int row = brow0 + h * 32;
            Bs[nxt][bkc + 0][row] = br[h].x; Bs[nxt][bkc + 1][row] = br[h].y;
            Bs[nxt][bkc + 2][row] = br[h].z; Bs[nxt][bkc + 3][row] = br[h].w;
        }
        __syncthreads();
        cur = nxt;
    }

    // epilogue compute on last buffer
#pragma unroll
    for (int kk = 0; kk < 16; ++kk) {
        ulonglong2 a01 = *(const ulonglong2*)&As[cur][kk][ty * 8];
        ulonglong2 a23 = *(const ulonglong2*)&As[cur][kk][ty * 8 + 4];
        float4 b0 = *(const float4*)&Bs[cur][kk][tx * 8];
        float4 b1 = *(const float4*)&Bs[cur][kk][tx * 8 + 4];
        u64 bd[8];
        bd[0] = dup2(b0.x); bd[1] = dup2(b0.y);
        bd[2] = dup2(b0.z); bd[3] = dup2(b0.w);
        bd[4] = dup2(b1.x); bd[5] = dup2(b1.y);
        bd[6] = dup2(b1.z); bd[7] = dup2(b1.w);
        u64 ap[4] = {a01.x, a01.y, a23.x, a23.y};
#pragma unroll
        for (int i = 0; i < 4; ++i)
#pragma unroll
            for (int q = 0; q < 8; ++q) ffma2(acc[i][q], ap[i], bd[q]);
    }

    float bv[8];
#pragma unroll
    for (int q = 0; q < 8; ++q) {
        bv[q] = bias1[bn + tx * 8 + q];
        if (BIAS2) bv[q] += bias2[bn + tx * 8 + q];
    }
#pragma unroll
    for (int i = 0; i < 4; ++i) {
        float lo[8], hi[8];
#pragma unroll
        for (int q = 0; q < 8; ++q) {
            upk2(acc[i][q], lo[q], hi[q]);
            lo[q] += bv[q]; hi[q] += bv[q];
            if (RELU) { lo[q] = fmaxf(lo[q], 0.0f); hi[q] = fmaxf(hi[q], 0.0f); }
        }
        float* c0 = C + (size_t)(bm + ty * 8 + 2 * i) * N + bn + tx * 8;
        float* c1 = c0 + N;
        *(float4*)(c0 + 0) = make_float4(lo[0], lo[1], lo[2], lo[3]);
        *(float4*)(c0 + 4) = make_float4(lo[4], lo[5], lo[6], lo[7]);
        *(float4*)(c1 + 0) = make_float4(hi[0], hi[1], hi[2], hi[3]);
        *(float4*)(c1 + 4) = make_float4(hi[4], hi[5], hi[6], hi[7]);
    }
}

// ============================================================
// LSTM recurrence: one CTA per env (32 CTAs), 512 threads.
// ============================================================
#define LSTM_SMEM_BYTES (16 * 512 * 16 + 128 * 4 + 512 * 4)

__global__ void __launch_bounds__(512, 1)
lstm_kernel(const float* __restrict__ gx, const float* __restrict__ whh,
            const int* __restrict__ done, const float* __restrict__ h0,
            const float* __restrict__ c0, float* __restrict__ hid)
{
    extern __shared__ float sm[];
    float4* wp4  = (float4*)sm;                    // [16][512] float4
    float*  h_sh = sm + 16 * 512 * 4;              // 128
    float*  act  = h_sh + 128;                     // 512

    const int env = blockIdx.x;
    const int j = threadIdx.x;

    const float* wrow = whh + (size_t)j * 128;
    float wreg[64];
#pragma unroll
    for (int k = 0; k < 64; k += 4) {
        float4 v = *(const float4*)(wrow + k);
        wreg[k] = v.x; wreg[k + 1] = v.y; wreg[k + 2] = v.z; wreg[k + 3] = v.w;
    }
#pragma unroll
    for (int kk = 0; kk < 16; ++kk)
        wp4[kk * 512 + j] = *(const float4*)(wrow + 64 + kk * 4);

    float c = 0.0f, hprev = 0.0f;
    if (j < 128) {
        hprev = h0[env * 128 + j];
        c     = c0[env * 128 + j];
    }
    __syncthreads();

    for (int t = 0; t < TT; ++t) {
        if (j < 128) {
            float m = 1.0f - (float)done[t * BB + env];
            h_sh[j] = hprev * m;
            c *= m;
        }
        __syncthreads();

        float accv = gx[((size_t)t * BB + env) * 512 + j];
#pragma unroll
        for (int k = 0; k < 64; k += 4) {
            float4 hv = *(const float4*)&h_sh[k];
            accv += hv.x * wreg[k] + hv.y * wreg[k + 1]
                  + hv.z * wreg[k + 2] + hv.w * wreg[k + 3];
        }
#pragma unroll
        for (int kk = 0; kk < 16; ++kk) {
            float4 wv = wp4[kk * 512 + j];
            float4 hv = *(const float4*)&h_sh[64 + kk * 4];
            accv += wv.x * hv.x + wv.y * hv.y + wv.z * hv.z + wv.w * hv.w;
        }

        float a;
        if (j < 256 || j >= 384) a = 1.0f / (1.0f + expf(-accv));
        else                     a = tanhf(accv);
        act[j] = a;
        __syncthreads();

        if (j < 128) {
            float ig = act[j],       fg = act[128 + j];
            float gg = act[256 + j], og = act[384 + j];
            c = fg * c + ig * gg;
            hprev = og * tanhf(c);
            hid[((size_t)t * BB + env) * 128 + j] = hprev;
        }
    }
}

// ============================================================
// heads
// ============================================================
__global__ void __launch_bounds__(304, 4)
heads_kernel(const float* __restrict__ hid, const float* __restrict__ wa,
             const float* __restrict__ ba, const float* __restrict__ wc,
             const float* __restrict__ bc, float* __restrict__ out)
{
    __shared__ float wsh[19 * 128];
    __shared__ float hsh[16 * 128];
    __shared__ float bsh[19];

    const int t = threadIdx.x;
    const int rb = blockIdx.x * 16;

    for (int i = t; i < 18 * 128; i += 304) wsh[i] = wa[i];
    for (int i = t; i < 128; i += 304)      wsh[18 * 128 + i] = wc[i];
    for (int i = t; i < 2048; i += 304)     hsh[i] = hid[(size_t)rb * 128 + i];
    if (t < 18) bsh[t] = ba[t];
    if (t == 18) bsh[18] = bc[0];
    __syncthreads();

    const int r = t / 19, cidx = t % 19;
    float accv = bsh[cidx];
    const float* hr = &hsh[r * 128];
    const float* wr = &wsh[cidx * 128];
#pragma unroll
    for (int k = 0; k < 128; k += 4) {
        float4 hv = *(const float4*)(hr + k);
        float4 wv = *(const float4*)(wr + k);
        accv += hv.x * wv.x + hv.y * wv.y + hv.z * wv.z + hv.w * wv.w;
    }
    out[(size_t)(rb + r) * OUTC + cidx] = accv;
}

// ============================================================
// host launcher
// ============================================================
extern "C" void kernel_launch(void* const* d_in, const int* in_sizes, int n_in,
                              void* d_out, int out_size)
{
    const float* x    = (const float*)d_in[0];
    const int*   done = (const int*)  d_in[1];
    const float* h0   = (const float*)d_in[2];
    const float* c0   = (const float*)d_in[3];
    const float* w1   = (const float*)d_in[4];
    const float* b1   = (const float*)d_in[5];
    const float* w2   = (const float*)d_in[6];
    const float* b2   = (const float*)d_in[7];
    const float* w3   = (const float*)d_in[8];
    const float* b3   = (const float*)d_in[9];
    const float* wf   = (const float*)d_in[10];
    const float* bf   = (const float*)d_in[11];
    const float* w_ih = (const float*)d_in[12];
    const float* w_hh = (const float*)d_in[13];
    const float* b_ih = (const float*)d_in[14];
    const float* b_hh = (const float*)d_in[15];
    const float* wa   = (const float*)d_in[16];
    const float* ba   = (const float*)d_in[17];
    const float* wc   = (const float*)d_in[18];
    const float* bc   = (const float*)d_in[19];
    float* out = (float*)d_out;

    float *c1, *c2, *c3, *feat, *gx, *hidp, *w1r, *w2r, *w3r;
    cudaGetSymbolAddress((void**)&c1,   g_c1);
    cudaGetSymbolAddress((void**)&c2,   g_c2);
    cudaGetSymbolAddress((void**)&c3,   g_c3);
    cudaGetSymbolAddress((void**)&feat, g_feat);
    cudaGetSymbolAddress((void**)&gx,   g_gx);
    cudaGetSymbolAddress((void**)&hidp, g_hid);
    cudaGetSymbolAddress((void**)&w1r,  g_w1r);
    cudaGetSymbolAddress((void**)&w2r,  g_w2r);
    cudaGetSymbolAddress((void**)&w3r,  g_w3r);

    const int c1_smem = (14784 + 8192) * 4;               // 91904
    const int c2_smem = (32768 + 12800) * 4;              // 182272
    const int c3_smem = (36864 + 4 * C3_IMG_STRIDE) * 4;  // 230464
    cudaFuncSetAttribute(conv1_kernel, cudaFuncAttributeMaxDynamicSharedMemorySize, c1_smem);
    cudaFuncSetAttribute(conv2_kernel, cudaFuncAttributeMaxDynamicSharedMemorySize, c2_smem);
    cudaFuncSetAttribute(conv3_kernel, cudaFuncAttributeMaxDynamicSharedMemorySize, c3_smem);
    cudaFuncSetAttribute(lstm_kernel,  cudaFuncAttributeMaxDynamicSharedMemorySize, LSTM_SMEM_BYTES);

    reorder_w_kernel<<<(8192  + 255) / 256, 256>>>(w1, w1r, 256, 32, 1.0f / 255.0f);
    reorder_w_kernel<<<(32768 + 255) / 256, 256>>>(w2, w2r, 512, 64, 1.0f);
    reorder_w_kernel<<<(36864 + 255) / 256, 256>>>(w3, w3r, 576, 64, 1.0f);

    conv1_kernel<<<TB * 2, 512, c1_smem>>>(x, w1r, b1, c1);
    conv2_kernel<<<TB / 4, 256, c2_smem>>>(c1, w2r, b2, c2);
    conv3_kernel<<<TB / 4, 512, c3_smem>>>(c2, w3r, b3, c3);

    gemm_kernel<true, false><<<dim3(FEAT / 64, TB / 128), 128>>>(
        c3, wf, bf, nullptr, feat, TB, FEAT, 3136);

    gemm_kernel<false, true><<<dim3(512 / 64, TB / 128), 128>>>(
        feat, w_ih, b_ih, b_hh, gx, TB, 512, FEAT);

    lstm_kernel<<<BB, 512, LSTM_SMEM_BYTES>>>(gx, w_hh, done, h0, c0, hidp);

    heads_kernel<<<TB / 16, 304>>>(hidp, wa, ba, wc, bc, out);
}

// round 10
// speedup vs baseline: 1.2714x; 1.1348x over previous
#include <cuda_runtime.h>
#include <cuda_bf16.h>
#include <math.h>
#include <stdint.h>

// ---------------- problem constants ----------------
#define TT   128
#define BB   32
#define TB   (TT*BB)          // 4096
#define HID  128
#define FEAT 512
#define AA   18
#define OUTC (AA+1)           // 19

typedef unsigned long long u64;

// ---------------- packed f32x2 helpers (SASS FFMA2) ----------------
__device__ __forceinline__ u64 pk2(float x, float y) {
    u64 r; asm("mov.b64 %0, {%1, %2};" : "=l"(r) : "f"(x), "f"(y)); return r;
}
__device__ __forceinline__ u64 dup2(float x) { return pk2(x, x); }
__device__ __forceinline__ void ffma2(u64& d, u64 a, u64 b) {
    asm("fma.rn.f32x2 %0, %1, %2, %0;" : "+l"(d) : "l"(a), "l"(b));
}
__device__ __forceinline__ void upk2(u64 v, float& x, float& y) {
    asm("mov.b64 {%0, %1}, %2;" : "=f"(x), "=f"(y) : "l"(v));
}

// ---------------- HMMA helpers (base ISA: mma.sync + ldmatrix) ----------------
__device__ __forceinline__ uint32_t smem_u32(const void* p) {
    uint32_t a;
    asm("{ .reg .u64 t; cvta.to.shared.u64 t, %1; cvt.u32.u64 %0, t; }" : "=r"(a) : "l"(p));
    return a;
}
__device__ __forceinline__ void ldsm_x4(uint32_t* r, uint32_t addr) {
    asm volatile("ldmatrix.sync.aligned.m8n8.x4.shared.b16 {%0,%1,%2,%3}, [%4];"
        : "=r"(r[0]), "=r"(r[1]), "=r"(r[2]), "=r"(r[3]) : "r"(addr));
}
__device__ __forceinline__ void mma_bf16(float* d, const uint32_t* a, const uint32_t* b) {
    asm volatile("mma.sync.aligned.m16n8k16.row.col.f32.bf16.bf16.f32 "
        "{%0,%1,%2,%3}, {%4,%5,%6,%7}, {%8,%9}, {%0,%1,%2,%3};"
        : "+f"(d[0]), "+f"(d[1]), "+f"(d[2]), "+f"(d[3])
        : "r"(a[0]), "r"(a[1]), "r"(a[2]), "r"(a[3]), "r"(b[0]), "r"(b[1]));
}

// ---------------- scratch (static device allocations) ----------------
__device__ float g_c1[TB * 32 * 20 * 20];
__device__ float g_c2[TB * 64 * 9 * 9];
__device__ float g_c3[TB * 64 * 7 * 7];
__device__ float g_feat[TB * FEAT];
__device__ float g_gx[TB * 4 * HID];
__device__ float g_hid[TB * HID];
__device__ float g_w1r[8192];
__device__ float g_w2r[32768];
__device__ float g_w3r[36864];
// bf16 hi/lo split operands (plain row-major)
__device__ __nv_bfloat16 g_a1h[TB * 3136], g_a1l[TB * 3136];      // c3
__device__ __nv_bfloat16 g_b1h[FEAT * 3136], g_b1l[FEAT * 3136];  // wf
__device__ __nv_bfloat16 g_a2h[TB * FEAT], g_a2l[TB * FEAT];      // feat
__device__ __nv_bfloat16 g_b2h[FEAT * FEAT], g_b2l[FEAT * FEAT];  // w_ih

// ============================================================
// weight reorder: out[r*OC + oc] = in[oc*R + r] * scale
// ============================================================
__global__ void reorder_w_kernel(const float* __restrict__ in,
                                 float* __restrict__ out,
                                 int R, int OC, float scale)
{
    int i = blockIdx.x * 256 + threadIdx.x;
    if (i >= R * OC) return;
    int oc = i / R, r = i - oc * R;
    out[r * OC + oc] = in[oc * R + r] * scale;
}

// ============================================================
// hi/lo bf16 convert, plain row-major
// ============================================================
__global__ void convert_hl_kernel(const float* __restrict__ src,
                                  __nv_bfloat16* __restrict__ hi,
                                  __nv_bfloat16* __restrict__ lo,
                                  int total)
{
    for (int i = blockIdx.x * 256 + threadIdx.x; i < total; i += gridDim.x * 256) {
        float v = src[i];
        __nv_bfloat16 h = __float2bfloat16(v);
        __nv_bfloat16 l = __float2bfloat16(v - __bfloat162float(h));
        hi[i] = h; lo[i] = l;
    }
}

// ============================================================
// HMMA bf16-split GEMM: C[M,Ntot] = A[M,K] @ B[Ntot,K]^T + bias (+bias2)
// D += Ah*Bh + Ah*Bl + Al*Bh  (fp32 accumulators)
// CTA 128x64, 256 threads, warps 2(M)x4(N) -> warp tile 64x16.
// K chunks of 64 in smem; smem rows padded to 72 bf16 (conflict-free LDSM).
// ============================================================
#define PAD 72
#define SM_GA   256                               // bias: [0,256)
#define SM_GAL  (SM_GA  + 128 * PAD * 2)          // 18432 each
#define SM_GBH  (SM_GAL + 128 * PAD * 2)
#define SM_GBL  (SM_GBH + 64 * PAD * 2)
#define MM_SMEM (SM_GBL + 64 * PAD * 2)           // 55552 + 256

template <bool RELU, bool BIAS2>
__global__ void __launch_bounds__(256, 2)
mma_gemm_kernel(const __nv_bfloat16* __restrict__ Ah, const __nv_bfloat16* __restrict__ Al,
                const __nv_bfloat16* __restrict__ Bh, const __nv_bfloat16* __restrict__ Bl,
                const float* __restrict__ bias1, const float* __restrict__ bias2,
                float* __restrict__ C, int K, int Ntot)
{
    extern __shared__ char smc[];
    float* sbias = (float*)smc;
    const uint32_t sb = smem_u32(smc);
    const uint32_t sAh = sb + SM_GA,  sAl = sb + SM_GAL;
    const uint32_t sBh = sb + SM_GBH, sBl = sb + SM_GBL;

    const int tid = threadIdx.x, wid = tid >> 5, lid = tid & 31;
    const int bm = blockIdx.y * 128, bn = blockIdx.x * 64;
    const int wm = wid >> 2, wn = wid & 3;     // warp tile: (wm*64, wn*16)

    if (tid < 64) {
        float bv = bias1[bn + tid];
        if (BIAS2) bv += bias2[bn + tid];
        sbias[tid] = bv;
    }

    // ldmatrix lane address components
    const int arow = lid & 15;
    const int acol = (lid & 16) ? 8 : 0;                   // A, B-as-A pattern
    const int brow = (lid & 7) | ((lid & 16) >> 1);        // B x4: n row
    const int bcol = (lid & 8) ? 8 : 0;                    // B x4: k block

    float acc[4][2][4];
#pragma unroll
    for (int mi = 0; mi < 4; ++mi)
#pragma unroll
        for (int ni = 0; ni < 2; ++ni)
#pragma unroll
            for (int q = 0; q < 4; ++q) acc[mi][ni][q] = 0.0f;

    for (int kb = 0; kb < K; kb += 64) {
        // ---- fill smem (row-major gmem, padded rows in smem) ----
        {
            char* base = smc;
#pragma unroll
            for (int h = 0; h < 4; ++h) {              // A hi: 1024 float4
                int i = tid + h * 256;
                int row = i >> 3, c = i & 7;
                *(float4*)(base + SM_GA + row * (PAD * 2) + c * 16) =
                    *(const float4*)(Ah + (size_t)(bm + row) * K + kb + c * 8);
            }
#pragma unroll
            for (int h = 0; h < 4; ++h) {              // A lo
                int i = tid + h * 256;
                int row = i >> 3, c = i & 7;
                *(float4*)(base + SM_GAL + row * (PAD * 2) + c * 16) =
                    *(const float4*)(Al + (size_t)(bm + row) * K + kb + c * 8);
            }
#pragma unroll
            for (int h = 0; h < 2; ++h) {              // B hi: 512 float4
                int i = tid + h * 256;
                int row = i >> 3, c = i & 7;
                *(float4*)(base + SM_GBH + row * (PAD * 2) + c * 16) =
                    *(const float4*)(Bh + (size_t)(bn + row) * K + kb + c * 8);
            }
#pragma unroll
            for (int h = 0; h < 2; ++h) {              // B lo
                int i = tid + h * 256;
                int row = i >> 3, c = i & 7;
                *(float4*)(base + SM_GBL + row * (PAD * 2) + c * 16) =
                    *(const float4*)(Bl + (size_t)(bn + row) * K + kb + c * 8);
            }
        }
        __syncthreads();

#pragma unroll
        for (int ks = 0; ks < 4; ++ks) {
            const int k0 = ks * 16;
            uint32_t ah[4][4], al[4][4], bh[4], bl[4];
#pragma unroll
            for (int mi = 0; mi < 4; ++mi) {
                uint32_t ra = (uint32_t)((wm * 64 + mi * 16 + arow) * PAD + k0 + acol) * 2;
                ldsm_x4(ah[mi], sAh + ra);
                ldsm_x4(al[mi], sAl + ra);
            }
            {
                uint32_t rb = (uint32_t)((wn * 16 + brow) * PAD + k0 + bcol) * 2;
                ldsm_x4(bh, sBh + rb);
                ldsm_x4(bl, sBl + rb);
            }
#pragma unroll
            for (int mi = 0; mi < 4; ++mi)
#pragma unroll
                for (int ni = 0; ni < 2; ++ni) {
                    mma_bf16(acc[mi][ni], ah[mi], &bh[ni * 2]);
                    mma_bf16(acc[mi][ni], ah[mi], &bl[ni * 2]);
                    mma_bf16(acc[mi][ni], al[mi], &bh[ni * 2]);
                }
        }
        __syncthreads();
    }

    // ---- epilogue ----
    const int r = lid >> 2, c2 = (lid & 3) * 2;
#pragma unroll
    for (int mi = 0; mi < 4; ++mi)
#pragma unroll
        for (int ni = 0; ni < 2; ++ni) {
            int nloc = wn * 16 + ni * 8 + c2;
            float b0 = sbias[nloc], b1 = sbias[nloc + 1];
            int m0 = bm + wm * 64 + mi * 16 + r;
            float v0 = acc[mi][ni][0] + b0, v1 = acc[mi][ni][1] + b1;
            float v2 = acc[mi][ni][2] + b0, v3 = acc[mi][ni][3] + b1;
            if (RELU) {
                v0 = fmaxf(v0, 0.0f); v1 = fmaxf(v1, 0.0f);
                v2 = fmaxf(v2, 0.0f); v3 = fmaxf(v3, 0.0f);
            }
            *(float2*)(C + (size_t)m0 * Ntot + bn + nloc)       = make_float2(v0, v1);
            *(float2*)(C + (size_t)(m0 + 8) * Ntot + bn + nloc) = make_float2(v2, v3);
        }
}

// ============================================================
// conv1 [R6, measured 693us]
// ============================================================
__global__ void __launch_bounds__(512, 2)
conv1_kernel(const float* __restrict__ x, const float* __restrict__ wr,
             const float* __restrict__ b, float* __restrict__ out)
{
    extern __shared__ float sm[];
    float* img = sm;            // 14784
    float* ws  = sm + 14784;    // 8192

    const int n = blockIdx.x >> 1, half = blockIdx.x & 1;
    const int t = threadIdx.x;
    const int r0 = half * 40;

    const float4* xg4 = (const float4*)(x + (size_t)n * 28224);
    float4* img4 = (float4*)img;
#pragma unroll 4
    for (int i = t; i < 3696; i += 512) {
        int ch = i / 924, rr = i - ch * 924;
        img4[i] = xg4[ch * 1764 + r0 * 21 + rr];
    }
    const float4* wg = (const float4*)wr;
    float4* ws4 = (float4*)ws;
#pragma unroll
    for (int i = t; i < 2048; i += 512) ws4[i] = wg[i];
    __syncthreads();

    const int ocg = t >> 7, p = t & 127;
    if (p >= 100) return;
    const int oyl = p / 10, xg = p % 10;

    u64 acc[2][4];
#pragma unroll
    for (int q = 0; q < 4; ++q) {
        u64 bq = pk2(b[ocg * 8 + 2 * q], b[ocg * 8 + 2 * q + 1]);
        acc[0][q] = bq; acc[1][q] = bq;
    }

#pragma unroll
    for (int ic = 0; ic < 4; ++ic) {
#pragma unroll
        for (int ky = 0; ky < 8; ++ky) {
            const float* row = &img[ic * 3696 + (oyl * 4 + ky) * 84 + xg * 8];
            float rv[12];
            *(float4*)&rv[0] = *(const float4*)&row[0];
            *(float4*)&rv[4] = *(const float4*)&row[4];
            *(float4*)&rv[8] = *(const float4*)&row[8];
            const float* wb = &ws[((ic * 8 + ky) * 8) * 32 + ocg * 8];
#pragma unroll
            for (int kx = 0; kx < 8; ++kx) {
                ulonglong2 w01 = *(const ulonglong2*)&wb[kx * 32];
                ulonglong2 w23 = *(const ulonglong2*)&wb[kx * 32 + 4];
                u64 v0 = dup2(rv[kx]);
                u64 v1 = dup2(rv[4 + kx]);
                ffma2(acc[0][0], v0, w01.x); ffma2(acc[0][1], v0, w01.y);
                ffma2(acc[0][2], v0, w23.x); ffma2(acc[0][3], v0, w23.y);
                ffma2(acc[1][0], v1, w01.x); ffma2(acc[1][1], v1, w01.y);
                ffma2(acc[1][2], v1, w23.x); ffma2(acc[1][3], v1, w23.y);
            }
        }
    }
    float* op = out + (size_t)n * 12800 + (half * 10 + oyl) * 20 + xg * 2;
#pragma unroll
    for (int q = 0; q < 4; ++q) {
        float lo0, hi0, lo1, hi1;
        upk2(acc[0][q], lo0, hi0);
        upk2(acc[1][q], lo1, hi1);
        int oc0 = ocg * 8 + 2 * q;
        *(float2*)(op + (size_t)oc0 * 400)       = make_float2(fmaxf(lo0, 0.0f), fmaxf(lo1, 0.0f));
        *(float2*)(op + (size_t)(oc0 + 1) * 400) = make_float2(fmaxf(hi0, 0.0f), fmaxf(hi1, 0.0f));
    }
}

// ============================================================
// conv2 [R6/R3, known-good]
// ============================================================
__global__ void __launch_bounds__(256, 1)
conv2_kernel(const float* __restrict__ in, const float* __restrict__ wr,
             const float* __restrict__ b, float* __restrict__ out)
{
    extern __shared__ float sm[];
    float* ws  = sm;            // 32768
    float* img = sm + 32768;    // 12800

    const int t = threadIdx.x;
    const float4* wg = (const float4*)wr;
    float4* ws4 = (float4*)ws;
#pragma unroll
    for (int i = t; i < 8192; i += 256) ws4[i] = wg[i];

    const int ocg = t >> 5, sp = t & 31;
    const bool act = sp < 27;
    const int oy = sp / 3, xg = sp % 3;

    u64 bia[4];
#pragma unroll
    for (int q = 0; q < 4; ++q)
        bia[q] = pk2(b[ocg * 8 + 2 * q], b[ocg * 8 + 2 * q + 1]);

    for (int im = 0; im < 4; ++im) {
        const int n = blockIdx.x * 4 + im;
        __syncthreads();
        const float4* ig = (const float4*)(in + (size_t)n * 12800);
        float4* img4 = (float4*)img;
#pragma unroll
        for (int i = t; i < 3200; i += 256) img4[i] = ig[i];
        __syncthreads();

        if (act) {
            u64 acc[3][4];
#pragma unroll
            for (int i = 0; i < 3; ++i)
#pragma unroll
                for (int q = 0; q < 4; ++q) acc[i][q] = bia[q];

            for (int ic = 0; ic < 32; ++ic) {
#pragma unroll
                for (int ky = 0; ky < 4; ++ky) {
                    const float* row = &img[ic * 400 + (oy * 2 + ky) * 20 + xg * 6];
                    float rv[8];
#pragma unroll
                    for (int j = 0; j < 4; ++j)
                        *(float2*)&rv[j * 2] = *(const float2*)&row[j * 2];
                    const float* wb = &ws[((ic * 4 + ky) * 4) * 64 + ocg * 8];
#pragma unroll
                    for (int kx = 0; kx < 4; ++kx) {
                        ulonglong2 w01 = *(const ulonglong2*)&wb[kx * 64];
                        ulonglong2 w23 = *(const ulonglong2*)&wb[kx * 64 + 4];
#pragma unroll
                        for (int i = 0; i < 3; ++i) {
                            u64 v = dup2(rv[i * 2 + kx]);
                            ffma2(acc[i][0], v, w01.x);
                            ffma2(acc[i][1], v, w01.y);
                            ffma2(acc[i][2], v, w23.x);
                            ffma2(acc[i][3], v, w23.y);
                        }
                    }
                }
            }
            float* op = out + (size_t)n * 5184 + oy * 9 + xg * 3;
#pragma unroll
            for (int q = 0; q < 4; ++q) {
#pragma unroll
                for (int i = 0; i < 3; ++i) {
                    float lo, hi; upk2(acc[i][q], lo, hi);
                    op[(ocg * 8 + 2 * q + 0) * 81 + i] = fmaxf(lo, 0.0f);
                    op[(ocg * 8 + 2 * q + 1) * 81 + i] = fmaxf(hi, 0.0f);
                }
            }
        }
    }
}

// ============================================================
// conv3 [R6]
// ============================================================
#define C3_IMG_STRIDE 5188

__global__ void __launch_bounds__(512, 1)
conv3_kernel(const float* __restrict__ in, const float* __restrict__ wr,
             const float* __restrict__ b, float* __restrict__ out)
{
    extern __shared__ float sm[];
    float* ws  = sm;                 // 36864
    float* img = sm + 36864;         // 4 * 5188

    const int t = threadIdx.x;
    const float4* wg = (const float4*)wr;
    float4* ws4 = (float4*)ws;
#pragma unroll
    for (int i = t; i < 9216; i += 512) ws4[i] = wg[i];

    const int n0 = blockIdx.x * 4;
    const float4* ig = (const float4*)(in + (size_t)n0 * 5184);
#pragma unroll
    for (int i = t; i < 5184; i += 512) {
        int im = i / 1296, rr = i - im * 1296;
        ((float4*)(img + im * C3_IMG_STRIDE))[rr] = ig[im * 1296 + rr];
    }
    __syncthreads();

    const int ocg = t >> 5, sub = t & 31;
    const int imgi = sub >> 3, oy = sub & 7;
    if (oy >= 7) return;

    u64 bia[2];
    bia[0] = pk2(b[ocg * 4 + 0], b[ocg * 4 + 1]);
    bia[1] = pk2(b[ocg * 4 + 2], b[ocg * 4 + 3]);

    const float* ib = &img[imgi * C3_IMG_STRIDE];
    u64 acc[7][2];
#pragma unroll
    for (int i = 0; i < 7; ++i) { acc[i][0] = bia[0]; acc[i][1] = bia[1]; }

    for (int ic = 0; ic < 64; ++ic) {
#pragma unroll
        for (int ky = 0; ky < 3; ++ky) {
            const float* row = &ib[ic * 81 + (oy + ky) * 9];
            u64 rd[9];
#pragma unroll
            for (int c = 0; c < 9; ++c) rd[c] = dup2(row[c]);
            const float* wb = &ws[(ic * 9 + ky * 3) * 64 + ocg * 4];
#pragma unroll
            for (int kx = 0; kx < 3; ++kx) {
                ulonglong2 wv = *(const ulonglong2*)&wb[kx * 64];
#pragma unroll
                for (int ox = 0; ox < 7; ++ox) {
                    ffma2(acc[ox][0], rd[ox + kx], wv.x);
                    ffma2(acc[ox][1], rd[ox + kx], wv.y);
                }
            }
        }
    }
    float* op = out + (size_t)(n0 + imgi) * 3136 + oy * 7;
#pragma unroll
    for (int q = 0; q < 2; ++q) {
#pragma unroll
        for (int ox = 0; ox < 7; ++ox) {
            float lo, hi; upk2(acc[ox][q], lo, hi);
            op[(ocg * 4 + 2 * q + 0) * 49 + ox] = fmaxf(lo, 0.0f);
            op[(ocg * 4 + 2 * q + 1) * 49 + ox] = fmaxf(hi, 0.0f);
        }
    }
}

// ============================================================
// LSTM recurrence: one CTA per env (32 CTAs), 512 threads.
// ============================================================
#define LSTM_SMEM_BYTES (16 * 512 * 16 + 128 * 4 + 512 * 4)

__global__ void __launch_bounds__(512, 1)
lstm_kernel(const float* __restrict__ gx, const float* __restrict__ whh,
            const int* __restrict__ done, const float* __restrict__ h0,
            const float* __restrict__ c0, float* __restrict__ hid)
{
    extern __shared__ float sm[];
    float4* wp4  = (float4*)sm;
    float*  h_sh = sm + 16 * 512 * 4;
    float*  act  = h_sh + 128;

    const int env = blockIdx.x;
    const int j = threadIdx.x;

    const float* wrow = whh + (size_t)j * 128;
    float wreg[64];
#pragma unroll
    for (int k = 0; k < 64; k += 4) {
        float4 v = *(const float4*)(wrow + k);
        wreg[k] = v.x; wreg[k + 1] = v.y; wreg[k + 2] = v.z; wreg[k + 3] = v.w;
    }
#pragma unroll
    for (int kk = 0; kk < 16; ++kk)
        wp4[kk * 512 + j] = *(const float4*)(wrow + 64 + kk * 4);

    float c = 0.0f, hprev = 0.0f;
    if (j < 128) {
        hprev = h0[env * 128 + j];
        c     = c0[env * 128 + j];
    }
    __syncthreads();

    for (int t = 0; t < TT; ++t) {
        if (j < 128) {
            float m = 1.0f - (float)done[t * BB + env];
            h_sh[j] = hprev * m;
            c *= m;
        }
        __syncthreads();

        float accv = gx[((size_t)t * BB + env) * 512 + j];
#pragma unroll
        for (int k = 0; k < 64; k += 4) {
            float4 hv = *(const float4*)&h_sh[k];
            accv += hv.x * wreg[k] + hv.y * wreg[k + 1]
                  + hv.z * wreg[k + 2] + hv.w * wreg[k + 3];
        }
#pragma unroll
        for (int kk = 0; kk < 16; ++kk) {
            float4 wv = wp4[kk * 512 + j];
            float4 hv = *(const float4*)&h_sh[64 + kk * 4];
            accv += wv.x * hv.x + wv.y * hv.y + wv.z * hv.z + wv.w * hv.w;
        }

        float a;
        if (j < 256 || j >= 384) a = 1.0f / (1.0f + expf(-accv));
        else                     a = tanhf(accv);
        act[j] = a;
        __syncthreads();

        if (j < 128) {
            float ig = act[j],       fg = act[128 + j];
            float gg = act[256 + j], og = act[384 + j];
            c = fg * c + ig * gg;
            hprev = og * tanhf(c);
            hid[((size_t)t * BB + env) * 128 + j] = hprev;
        }
    }
}

// ============================================================
// heads
// ============================================================
__global__ void __launch_bounds__(304, 4)
heads_kernel(const float* __restrict__ hid, const float* __restrict__ wa,
             const float* __restrict__ ba, const float* __restrict__ wc,
             const float* __restrict__ bc, float* __restrict__ out)
{
    __shared__ float wsh[19 * 128];
    __shared__ float hsh[16 * 128];
    __shared__ float bsh[19];

    const int t = threadIdx.x;
    const int rb = blockIdx.x * 16;

    for (int i = t; i < 18 * 128; i += 304) wsh[i] = wa[i];
    for (int i = t; i < 128; i += 304)      wsh[18 * 128 + i] = wc[i];
    for (int i = t; i < 2048; i += 304)     hsh[i] = hid[(size_t)rb * 128 + i];
    if (t < 18) bsh[t] = ba[t];
    if (t == 18) bsh[18] = bc[0];
    __syncthreads();

    const int r = t / 19, cidx = t % 19;
    float accv = bsh[cidx];
    const float* hr = &hsh[r * 128];
    const float* wr = &wsh[cidx * 128];
#pragma unroll
    for (int k = 0; k < 128; k += 4) {
        float4 hv = *(const float4*)(hr + k);
        float4 wv = *(const float4*)(wr + k);
        accv += hv.x * wv.x + hv.y * wv.y + hv.z * wv.z + hv.w * wv.w;
    }
    out[(size_t)(rb + r) * OUTC + cidx] = accv;
}

// ============================================================
// host launcher
// ============================================================
extern "C" void kernel_launch(void* const* d_in, const int* in_sizes, int n_in,
                              void* d_out, int out_size)
{
    const float* x    = (const float*)d_in[0];
    const int*   done = (const int*)  d_in[1];
    const float* h0   = (const float*)d_in[2];
    const float* c0   = (const float*)d_in[3];
    const float* w1   = (const float*)d_in[4];
    const float* b1   = (const float*)d_in[5];
    const float* w2   = (const float*)d_in[6];
    const float* b2   = (const float*)d_in[7];
    const float* w3   = (const float*)d_in[8];
    const float* b3   = (const float*)d_in[9];
    const float* wf   = (const float*)d_in[10];
    const float* bf   = (const float*)d_in[11];
    const float* w_ih = (const float*)d_in[12];
    const float* w_hh = (const float*)d_in[13];
    const float* b_ih = (const float*)d_in[14];
    const float* b_hh = (const float*)d_in[15];
    const float* wa   = (const float*)d_in[16];
    const float* ba   = (const float*)d_in[17];
    const float* wc   = (const float*)d_in[18];
    const float* bc   = (const float*)d_in[19];
    float* out = (float*)d_out;

    float *c1, *c2, *c3, *feat, *gx, *hidp, *w1r, *w2r, *w3r;
    cudaGetSymbolAddress((void**)&c1,   g_c1);
    cudaGetSymbolAddress((void**)&c2,   g_c2);
    cudaGetSymbolAddress((void**)&c3,   g_c3);
    cudaGetSymbolAddress((void**)&feat, g_feat);
    cudaGetSymbolAddress((void**)&gx,   g_gx);
    cudaGetSymbolAddress((void**)&hidp, g_hid);
    cudaGetSymbolAddress((void**)&w1r,  g_w1r);
    cudaGetSymbolAddress((void**)&w2r,  g_w2r);
    cudaGetSymbolAddress((void**)&w3r,  g_w3r);
    __nv_bfloat16 *a1h, *a1l, *b1h, *b1l, *a2h, *a2l, *b2h, *b2l;
    cudaGetSymbolAddress((void**)&a1h, g_a1h);
    cudaGetSymbolAddress((void**)&a1l, g_a1l);
    cudaGetSymbolAddress((void**)&b1h, g_b1h);
    cudaGetSymbolAddress((void**)&b1l, g_b1l);
    cudaGetSymbolAddress((void**)&a2h, g_a2h);
    cudaGetSymbolAddress((void**)&a2l, g_a2l);
    cudaGetSymbolAddress((void**)&b2h, g_b2h);
    cudaGetSymbolAddress((void**)&b2l, g_b2l);

    const int c1_smem = (14784 + 8192) * 4;
    const int c2_smem = (32768 + 12800) * 4;
    const int c3_smem = (36864 + 4 * C3_IMG_STRIDE) * 4;
    cudaFuncSetAttribute(conv1_kernel, cudaFuncAttributeMaxDynamicSharedMemorySize, c1_smem);
    cudaFuncSetAttribute(conv2_kernel, cudaFuncAttributeMaxDynamicSharedMemorySize, c2_smem);
    cudaFuncSetAttribute(conv3_kernel, cudaFuncAttributeMaxDynamicSharedMemorySize, c3_smem);
    cudaFuncSetAttribute(lstm_kernel,  cudaFuncAttributeMaxDynamicSharedMemorySize, LSTM_SMEM_BYTES);
    cudaFuncSetAttribute(mma_gemm_kernel<true,  false>, cudaFuncAttributeMaxDynamicSharedMemorySize, MM_SMEM);
    cudaFuncSetAttribute(mma_gemm_kernel<false, true>,  cudaFuncAttributeMaxDynamicSharedMemorySize, MM_SMEM);

    reorder_w_kernel<<<(8192  + 255) / 256, 256>>>(w1, w1r, 256, 32, 1.0f / 255.0f);
    reorder_w_kernel<<<(32768 + 255) / 256, 256>>>(w2, w2r, 512, 64, 1.0f);
    reorder_w_kernel<<<(36864 + 255) / 256, 256>>>(w3, w3r, 576, 64, 1.0f);

    // weight hi/lo converts
    convert_hl_kernel<<<2048, 256>>>(wf,   b1h, b1l, FEAT * 3136);
    convert_hl_kernel<<<512,  256>>>(w_ih, b2h, b2l, FEAT * FEAT);

    conv1_kernel<<<TB * 2, 512, c1_smem>>>(x, w1r, b1, c1);
    conv2_kernel<<<TB / 4, 256, c2_smem>>>(c1, w2r, b2, c2);
    conv3_kernel<<<TB / 4, 512, c3_smem>>>(c2, w3r, b3, c3);

    // feat = relu(c3 @ wf^T + bf)  via HMMA bf16-split (K=3136)
    convert_hl_kernel<<<4096, 256>>>(c3, a1h, a1l, TB * 3136);
    mma_gemm_kernel<true, false><<<dim3(FEAT / 64, TB / 128), 256, MM_SMEM>>>(
        a1h, a1l, b1h, b1l, bf, nullptr, feat, 3136, FEAT);

    // gx = feat @ w_ih^T + b_ih + b_hh  via HMMA bf16-split (K=512)
    convert_hl_kernel<<<2048, 256>>>(feat, a2h, a2l, TB * FEAT);
    mma_gemm_kernel<false, true><<<dim3(FEAT / 64, TB / 128), 256, MM_SMEM>>>(
        a2h, a2l, b2h, b2l, b_ih, b_hh, gx, FEAT, FEAT);

    lstm_kernel<<<BB, 512, LSTM_SMEM_BYTES>>>(gx, w_hh, done, h0, c0, hidp);

    heads_kernel<<<TB / 16, 304>>>(hidp, wa, ba, wc, bc, out);
}